// round 6
// baseline (speedup 1.0000x reference)
#include <cuda_runtime.h>

#define NPTS   4096
#define DOUT   3
#define IBLK   128
#define JCHUNK 128
#define NIB    (NPTS / IBLK)    // 32
#define NJB    (NPTS / JCHUNK)  // 32

// Partial sums: [jb][i][{num012,_},{den012,_}] — fully overwritten every
// replay (no reset needed, no atomics). 32*4096*2*16B = 4 MB, L2-resident.
__device__ float4 g_part[NJB * NPTS * 2];

__device__ __forceinline__ float ex2f(float x) {
    float y;
    asm("ex2.approx.ftz.f32 %0, %1;" : "=f"(y) : "f"(x));
    return y;
}

// Identical projection code path for query-side (x) and train-side (train_X)
// so row i of both is bitwise-equal -> self-pair kernel value is exactly 1.0,
// removed exactly in finalize.
__device__ __forceinline__ void proj3(float4 v, const float* __restrict__ w, float s,
                                      float& f0, float& f1, float& f2) {
    f0 = (v.x * w[0] + v.y * w[1] + v.z * w[2]  + v.w * w[3])  * s;
    f1 = (v.x * w[4] + v.y * w[5] + v.z * w[6]  + v.w * w[7])  * s;
    f2 = (v.x * w[8] + v.y * w[9] + v.z * w[10] + v.w * w[11]) * s;
}

__global__ void __launch_bounds__(IBLK) pair_kernel(const float* __restrict__ x,
                                                    const float* __restrict__ tx,
                                                    const float* __restrict__ Y,
                                                    const float* __restrict__ W,
                                                    const float* __restrict__ h) {
    __shared__ float4 sh[2 * JCHUNK];  // 4 KB: per-j {F0,F1,F2,_},{Y0,Y1,Y2,_}

    int tid = threadIdx.x;
    int i   = blockIdx.x * IBLK + tid;
    int j0  = blockIdx.y * JCHUNK;

    // exp(-0.5*((a-b)/h)^2) = ex2(-(c*(a-b))^2), c = sqrt(0.5*log2(e))/h
    float s = 0.8493218002880191f / __ldg(h);

    float w[12];
#pragma unroll
    for (int k = 0; k < 12; k++) w[k] = __ldg(&W[k]);

    // Stage this CTA's j-chunk: project train_X rows + fetch Y rows.
    {
        int j = j0 + tid;  // JCHUNK == IBLK
        float4 tv = reinterpret_cast<const float4*>(tx)[j];
        float t0, t1, t2;
        proj3(tv, w, s, t0, t1, t2);
        sh[2 * tid]     = make_float4(t0, t1, t2, 0.0f);
        sh[2 * tid + 1] = make_float4(__ldg(&Y[j * 3 + 0]),
                                      __ldg(&Y[j * 3 + 1]),
                                      __ldg(&Y[j * 3 + 2]), 0.0f);
    }

    // This thread's query projection (identical code path as train side).
    float4 xv = reinterpret_cast<const float4*>(x)[i];
    float q0, q1, q2;
    proj3(xv, w, s, q0, q1, q2);

    float n0 = 0.f, n1 = 0.f, n2 = 0.f;
    float d0 = 0.f, d1 = 0.f, d2 = 0.f;

    __syncthreads();

#pragma unroll 8
    for (int j = 0; j < JCHUNK; j++) {
        float4 f  = sh[2 * j];      // broadcast LDS.128
        float4 yv = sh[2 * j + 1];  // broadcast LDS.128
        float u0 = f.x - q0;  float k0 = ex2f(-u0 * u0);
        float u1 = f.y - q1;  float k1 = ex2f(-u1 * u1);
        float u2 = f.z - q2;  float k2 = ex2f(-u2 * u2);
        n0 = fmaf(k0, yv.x, n0);  d0 += k0;
        n1 = fmaf(k1, yv.y, n1);  d1 += k1;
        n2 = fmaf(k2, yv.z, n2);  d2 += k2;
    }

    int base = (blockIdx.y * NPTS + i) * 2;
    g_part[base]     = make_float4(n0, n1, n2, 0.0f);
    g_part[base + 1] = make_float4(d0, d1, d2, 0.0f);
}

__global__ void __launch_bounds__(IBLK) finalize_kernel(const float* __restrict__ Y,
                                                        float* __restrict__ out) {
    int i = blockIdx.x * IBLK + threadIdx.x;

    float n0 = 0.f, n1 = 0.f, n2 = 0.f;
    float d0 = 0.f, d1 = 0.f, d2 = 0.f;
#pragma unroll
    for (int jb = 0; jb < NJB; jb++) {
        int base = (jb * NPTS + i) * 2;
        float4 a = g_part[base];
        float4 b = g_part[base + 1];
        n0 += a.x;  n1 += a.y;  n2 += a.z;
        d0 += b.x;  d1 += b.y;  d2 += b.z;
    }

    // Remove exact self-pair contribution (K_ii == 1.0 bitwise).
    float y0 = __ldg(&Y[i * 3 + 0]);
    float y1 = __ldg(&Y[i * 3 + 1]);
    float y2 = __ldg(&Y[i * 3 + 2]);
    out[i * 3 + 0] = (n0 - y0) / (d0 - 1.0f);
    out[i * 3 + 1] = (n1 - y1) / (d1 - 1.0f);
    out[i * 3 + 2] = (n2 - y2) / (d2 - 1.0f);
}

extern "C" void kernel_launch(void* const* d_in, const int* in_sizes, int n_in,
                              void* d_out, int out_size) {
    const float* x  = (const float*)d_in[0];
    const float* tx = (const float*)d_in[1];
    const float* Y  = (const float*)d_in[2];
    const float* W  = (const float*)d_in[3];
    const float* h  = (const float*)d_in[4];
    float* out = (float*)d_out;

    pair_kernel<<<dim3(NIB, NJB), IBLK>>>(x, tx, Y, W, h);
    finalize_kernel<<<NIB, IBLK>>>(Y, out);
}